// round 10
// baseline (speedup 1.0000x reference)
#include <cuda_runtime.h>
#include <cuda_bf16.h>

#define BB     4
#define NN     8192
#define CC     256
#define POOLN  2048
#define NBR    4
#define TILE_PTS   2048                  // smem tile: first 2048 points of the batch
#define TILE_FLOATS (TILE_PTS * 3)       // 24 KB
#define QPB    8                         // queries (warps) per block
#define SEG    (NN / 8)                  // 1024 points per warp segment

// Unconditional per-query flag, rewritten by every replay (no reset needed,
// no atomics, no counters).
__device__ int g_hard_flag[BB * POOLN];

__device__ __forceinline__ float decode_radius(const int* radius_raw)
{
    const unsigned rv = (unsigned)__ldg(radius_raw);
    return (rv & 0x7F800000u) ? __int_as_float((int)rv) : (float)(int)rv;
}

// ---------------- Easy pass: 8 queries per block, smem vertex tile ----------------
__global__ __launch_bounds__(256)
void pool_easy_kernel(const float* __restrict__ verts,
                      const float* __restrict__ feat,
                      const int*   __restrict__ radius_raw,
                      const int*   __restrict__ sample_idx,
                      float* __restrict__ outV,
                      float* __restrict__ outF)
{
    __shared__ float s_tile[TILE_FLOATS];   // raw (x,y,z)*2048 of this batch

    const int wid  = threadIdx.x >> 5;
    const int lane = threadIdx.x & 31;
    const int qid  = blockIdx.x * QPB + wid;         // 0 .. BB*POOLN-1
    const int b    = qid >> 11;                      // / POOLN (uniform per block)
    const int s    = qid & (POOLN - 1);

    // Cooperative tile load: 1536 float4 slots, coalesced.
    {
        const float4* __restrict__ src =
            (const float4*)(verts + (size_t)b * NN * 3);
        float4* dst = (float4*)s_tile;
        #pragma unroll
        for (int i = 0; i < TILE_FLOATS / 4 / 256; i++)
            dst[threadIdx.x + 256 * i] = src[threadIdx.x + 256 * i];
    }

    const int n = sample_idx[s];
    const float* vb = verts + (size_t)b * NN * 3;
    const float qx = vb[n * 3 + 0];
    const float qy = vb[n * 3 + 1];
    const float qz = vb[n * 3 + 2];
    const float sqn = qx * qx + qy * qy + qz * qz;

    const float radius = decode_radius(radius_raw);
    const float r2 = radius * radius;

    // vertices_pool (always written here)
    if (lane < 3) {
        const float v = (lane == 0) ? qx : (lane == 1) ? qy : qz;
        outV[((size_t)b * POOLN + s) * 3 + lane] = v;
    }

    __syncthreads();

    // ---- scan smem tile, first NBR ascending qualifiers ----
    int idx[NBR];
    int cnt = 0;
    #pragma unroll
    for (int k = 0; k < NBR; k++) idx[k] = n;

    for (int base = 0; base < TILE_PTS; base += 128) {
        unsigned bal[4];
        #pragma unroll
        for (int t = 0; t < 4; t++) {
            const int p = base + t * 32 + lane;
            const float px = s_tile[3 * p + 0];
            const float py = s_tile[3 * p + 1];
            const float pz = s_tile[3 * p + 2];
            const float d = -2.0f * (px * qx + py * qy + pz * qz) + sqn
                            + (px * px + py * py + pz * pz);
            bal[t] = __ballot_sync(0xFFFFFFFFu, !(d > r2));
        }
        #pragma unroll
        for (int t = 0; t < 4; t++) {
            unsigned m = bal[t];
            while (m && cnt < NBR) {
                idx[cnt++] = base + t * 32 + (__ffs(m) - 1);
                m &= m - 1;
            }
        }
        if (cnt >= NBR) break;   // uniform (ballot-derived)
    }

    // Unconditional flag write: deterministic, replay-safe, atomic-free.
    if (lane == 0) g_hard_flag[qid] = (cnt < NBR) ? 1 : 0;
    if (cnt < NBR) return;       // hard pass will finish this query

    // ---- gather 4 feature rows (float4), max, store ----
    const float* fb = feat + (size_t)b * NN * CC;
    const float4* __restrict__ f0 = (const float4*)(fb + (size_t)idx[0] * CC);
    const float4* __restrict__ f1 = (const float4*)(fb + (size_t)idx[1] * CC);
    const float4* __restrict__ f2 = (const float4*)(fb + (size_t)idx[2] * CC);
    const float4* __restrict__ f3 = (const float4*)(fb + (size_t)idx[3] * CC);
    float4* __restrict__ fo = (float4*)(outF + ((size_t)b * POOLN + s) * CC);

    #pragma unroll
    for (int j = 0; j < CC / 128; j++) {
        const int c = lane + j * 32;
        float4 a = f0[c];
        const float4 v1 = f1[c], v2 = f2[c], v3 = f3[c];
        a.x = fmaxf(fmaxf(a.x, v1.x), fmaxf(v2.x, v3.x));
        a.y = fmaxf(fmaxf(a.y, v1.y), fmaxf(v2.y, v3.y));
        a.z = fmaxf(fmaxf(a.z, v1.z), fmaxf(v2.z, v3.z));
        a.w = fmaxf(fmaxf(a.w, v1.w), fmaxf(v2.w, v3.w));
        fo[c] = a;
    }
}

// ---------------- Hard pass: block k owns qids [8k, 8k+8); flag-driven ----------------
// No atomics, no counters, no fences. Each flagged query gets a full-N scan
// split into 8 coalesced warp segments with per-segment early exit, then a
// segment-order merge (ascending indices) by thread 0.
__global__ __launch_bounds__(256, 4)
void pool_hard_kernel(const float* __restrict__ verts,
                      const float* __restrict__ feat,
                      const int*   __restrict__ radius_raw,
                      const int*   __restrict__ sample_idx,
                      float* __restrict__ outF)
{
    const int wid  = threadIdx.x >> 5;
    const int lane = threadIdx.x & 31;

    __shared__ int s_flags[QPB];
    __shared__ int s_cnt[8];
    __shared__ int s_list[8][NBR];
    __shared__ int s_idx[NBR];

    if (threadIdx.x < QPB)
        s_flags[threadIdx.x] = g_hard_flag[blockIdx.x * QPB + threadIdx.x];
    __syncthreads();

    const float radius = decode_radius(radius_raw);
    const float r2 = radius * radius;

    #pragma unroll
    for (int w = 0; w < QPB; w++) {
        if (!s_flags[w]) continue;

        const int qid = blockIdx.x * QPB + w;
        const int b = qid >> 11;
        const int s = qid & (POOLN - 1);

        const int n = sample_idx[s];
        const float* vb = verts + (size_t)b * NN * 3;
        const float qx = vb[n * 3 + 0];
        const float qy = vb[n * 3 + 1];
        const float qz = vb[n * 3 + 2];
        const float sqn = qx * qx + qy * qy + qz * qz;

        // ---- warp scans its segment [wid*SEG, (wid+1)*SEG) ----
        int idx[NBR];
        int cnt = 0;
        const int seg = wid * SEG;

        for (int base = 0; base < SEG; base += 128) {
            unsigned bal[4];
            #pragma unroll
            for (int t = 0; t < 4; t++) {
                const int p = seg + base + t * 32 + lane;
                const float px = vb[3 * p + 0];
                const float py = vb[3 * p + 1];
                const float pz = vb[3 * p + 2];
                const float d = -2.0f * (px * qx + py * qy + pz * qz) + sqn
                                + (px * px + py * py + pz * pz);
                bal[t] = __ballot_sync(0xFFFFFFFFu, !(d > r2));
            }
            #pragma unroll
            for (int t = 0; t < 4; t++) {
                unsigned m = bal[t];
                while (m && cnt < NBR) {
                    idx[cnt++] = seg + base + t * 32 + (__ffs(m) - 1);
                    m &= m - 1;
                }
            }
            if (cnt >= NBR) break;   // uniform within warp
        }

        if (lane == 0) {
            s_cnt[wid] = cnt;
            #pragma unroll
            for (int k = 0; k < NBR; k++) s_list[wid][k] = (k < cnt) ? idx[k] : 0;
        }
        __syncthreads();

        // ---- merge: segments ascending, lists internally ascending ----
        if (threadIdx.x == 0) {
            int tot = 0;
            #pragma unroll
            for (int ww = 0; ww < 8; ww++) {
                const int cw = s_cnt[ww];
                for (int k = 0; k < cw && tot < NBR; k++)
                    s_idx[tot++] = s_list[ww][k];
                if (tot >= NBR) break;
            }
            // tot >= 1 always (self point qualifies in its own segment)
            for (int k = tot; k < NBR; k++) s_idx[k] = s_idx[0];
        }
        __syncthreads();

        // ---- gather + max with 64 threads ----
        if (threadIdx.x < CC / 4) {
            const int t = threadIdx.x;
            const float* fb = feat + (size_t)b * NN * CC;
            const float4 a0 = ((const float4*)(fb + (size_t)s_idx[0] * CC))[t];
            const float4 a1 = ((const float4*)(fb + (size_t)s_idx[1] * CC))[t];
            const float4 a2 = ((const float4*)(fb + (size_t)s_idx[2] * CC))[t];
            const float4 a3 = ((const float4*)(fb + (size_t)s_idx[3] * CC))[t];
            float4 r;
            r.x = fmaxf(fmaxf(a0.x, a1.x), fmaxf(a2.x, a3.x));
            r.y = fmaxf(fmaxf(a0.y, a1.y), fmaxf(a2.y, a3.y));
            r.z = fmaxf(fmaxf(a0.z, a1.z), fmaxf(a2.z, a3.z));
            r.w = fmaxf(fmaxf(a0.w, a1.w), fmaxf(a2.w, a3.w));
            ((float4*)(outF + ((size_t)b * POOLN + s) * CC))[t] = r;
        }
        __syncthreads();   // protect s_* reuse across queries
    }
}

extern "C" void kernel_launch(void* const* d_in, const int* in_sizes, int n_in,
                              void* d_out, int out_size)
{
    const float* verts      = (const float*)d_in[0];
    const float* feat       = (const float*)d_in[1];
    const int*   radius_raw = (const int*)  d_in[2];
    const int*   sample_idx = (const int*)  d_in[3];

    float* outV = (float*)d_out;
    float* outF = (float*)d_out + (size_t)BB * POOLN * 3;

    pool_easy_kernel<<<BB * POOLN / QPB, 256>>>(verts, feat, radius_raw,
                                                sample_idx, outV, outF);
    pool_hard_kernel<<<BB * POOLN / QPB, 256>>>(verts, feat, radius_raw,
                                                sample_idx, outF);
}

// round 11
// speedup vs baseline: 1.2999x; 1.2999x over previous
#include <cuda_runtime.h>
#include <cuda_bf16.h>

#define BB     4
#define NN     8192
#define CC     256
#define POOLN  2048
#define NBR    4
#define TILE_PTS   2048                  // smem tile: first 2048 points of the batch
#define TILE_FLOATS (TILE_PTS * 3)       // 24 KB
#define QPB    8                         // queries (warps) per block
#define SEG    (NN / 8)                  // 1024 points per warp segment

// Unconditional per-query flag, rewritten by every replay (no reset needed,
// no atomics, no counters).
__device__ int g_hard_flag[BB * POOLN];

__device__ __forceinline__ float decode_radius(const int* radius_raw)
{
    const unsigned rv = (unsigned)__ldg(radius_raw);
    return (rv & 0x7F800000u) ? __int_as_float((int)rv) : (float)(int)rv;
}

// ---------------- Easy pass: 8 queries per block, smem vertex tile ----------------
__global__ __launch_bounds__(256)
void pool_easy_kernel(const float* __restrict__ verts,
                      const float* __restrict__ feat,
                      const int*   __restrict__ radius_raw,
                      const int*   __restrict__ sample_idx,
                      float* __restrict__ outV,
                      float* __restrict__ outF)
{
    __shared__ float s_tile[TILE_FLOATS];   // raw (x,y,z)*2048 of this batch

    const int wid  = threadIdx.x >> 5;
    const int lane = threadIdx.x & 31;
    const int qid  = blockIdx.x * QPB + wid;         // 0 .. BB*POOLN-1
    const int b    = qid >> 11;                      // / POOLN (uniform per block)
    const int s    = qid & (POOLN - 1);

    // Cooperative tile load: 1536 float4 slots, coalesced.
    {
        const float4* __restrict__ src =
            (const float4*)(verts + (size_t)b * NN * 3);
        float4* dst = (float4*)s_tile;
        #pragma unroll
        for (int i = 0; i < TILE_FLOATS / 4 / 256; i++)
            dst[threadIdx.x + 256 * i] = src[threadIdx.x + 256 * i];
    }

    const int n = sample_idx[s];
    const float* vb = verts + (size_t)b * NN * 3;
    const float qx = vb[n * 3 + 0];
    const float qy = vb[n * 3 + 1];
    const float qz = vb[n * 3 + 2];
    const float sqn = qx * qx + qy * qy + qz * qz;

    const float radius = decode_radius(radius_raw);
    const float r2 = radius * radius;

    // vertices_pool (always written here)
    if (lane < 3) {
        const float v = (lane == 0) ? qx : (lane == 1) ? qy : qz;
        outV[((size_t)b * POOLN + s) * 3 + lane] = v;
    }

    __syncthreads();

    // ---- scan smem tile, first NBR ascending qualifiers ----
    int idx[NBR];
    int cnt = 0;
    #pragma unroll
    for (int k = 0; k < NBR; k++) idx[k] = n;

    for (int base = 0; base < TILE_PTS; base += 128) {
        unsigned bal[4];
        #pragma unroll
        for (int t = 0; t < 4; t++) {
            const int p = base + t * 32 + lane;
            const float px = s_tile[3 * p + 0];
            const float py = s_tile[3 * p + 1];
            const float pz = s_tile[3 * p + 2];
            const float d = -2.0f * (px * qx + py * qy + pz * qz) + sqn
                            + (px * px + py * py + pz * pz);
            bal[t] = __ballot_sync(0xFFFFFFFFu, !(d > r2));
        }
        #pragma unroll
        for (int t = 0; t < 4; t++) {
            unsigned m = bal[t];
            while (m && cnt < NBR) {
                idx[cnt++] = base + t * 32 + (__ffs(m) - 1);
                m &= m - 1;
            }
        }
        if (cnt >= NBR) break;   // uniform (ballot-derived)
    }

    // Unconditional flag write: deterministic, replay-safe, atomic-free.
    if (lane == 0) g_hard_flag[qid] = (cnt < NBR) ? 1 : 0;
    if (cnt < NBR) return;       // hard pass will finish this query

    // ---- gather 4 feature rows (float4), max, store ----
    const float* fb = feat + (size_t)b * NN * CC;
    const float4* __restrict__ f0 = (const float4*)(fb + (size_t)idx[0] * CC);
    const float4* __restrict__ f1 = (const float4*)(fb + (size_t)idx[1] * CC);
    const float4* __restrict__ f2 = (const float4*)(fb + (size_t)idx[2] * CC);
    const float4* __restrict__ f3 = (const float4*)(fb + (size_t)idx[3] * CC);
    float4* __restrict__ fo = (float4*)(outF + ((size_t)b * POOLN + s) * CC);

    #pragma unroll
    for (int j = 0; j < CC / 128; j++) {
        const int c = lane + j * 32;
        float4 a = f0[c];
        const float4 v1 = f1[c], v2 = f2[c], v3 = f3[c];
        a.x = fmaxf(fmaxf(a.x, v1.x), fmaxf(v2.x, v3.x));
        a.y = fmaxf(fmaxf(a.y, v1.y), fmaxf(v2.y, v3.y));
        a.z = fmaxf(fmaxf(a.z, v1.z), fmaxf(v2.z, v3.z));
        a.w = fmaxf(fmaxf(a.w, v1.w), fmaxf(v2.w, v3.w));
        fo[c] = a;
    }
}

// ---------------- Hard pass: block k owns qids [8k, 8k+8); flag-driven ----------------
// Pipelined scan: each lane builds a 32-bit qualifier mask over its 32
// lane-strided points (96 independent coalesced loads, no ballots in the
// load loop -> one L2 round trip), then cheap register ballots extract the
// first-4 ascending qualifiers. No atomics, no counters, no fences.
__global__ __launch_bounds__(256, 2)
void pool_hard_kernel(const float* __restrict__ verts,
                      const float* __restrict__ feat,
                      const int*   __restrict__ radius_raw,
                      const int*   __restrict__ sample_idx,
                      float* __restrict__ outF)
{
    const int wid  = threadIdx.x >> 5;
    const int lane = threadIdx.x & 31;

    __shared__ int s_flags[QPB];
    __shared__ int s_cnt[8];
    __shared__ int s_list[8][NBR];
    __shared__ int s_idx[NBR];

    if (threadIdx.x < QPB)
        s_flags[threadIdx.x] = g_hard_flag[blockIdx.x * QPB + threadIdx.x];
    __syncthreads();

    const float radius = decode_radius(radius_raw);
    const float r2 = radius * radius;

    for (int w = 0; w < QPB; w++) {          // uniform per block; usually 0-1 taken
        if (!s_flags[w]) continue;

        const int qid = blockIdx.x * QPB + w;
        const int b = qid >> 11;
        const int s = qid & (POOLN - 1);

        const int n = sample_idx[s];
        const float* vb = verts + (size_t)b * NN * 3;
        const float qx = vb[n * 3 + 0];
        const float qy = vb[n * 3 + 1];
        const float qz = vb[n * 3 + 2];
        const float sqn = qx * qx + qy * qy + qz * qz;

        const int seg = wid * SEG;           // warp's 1024-point segment

        // ---- build per-lane 32-bit qualifier mask (fully pipelined loads) ----
        unsigned lm = 0;
        #pragma unroll
        for (int j = 0; j < 32; j++) {
            const int p = seg + j * 32 + lane;
            const float px = vb[3 * p + 0];
            const float py = vb[3 * p + 1];
            const float pz = vb[3 * p + 2];
            const float d = -2.0f * (px * qx + py * qy + pz * qz) + sqn
                            + (px * px + py * py + pz * pz);
            lm |= ((unsigned)(!(d > r2))) << j;
        }

        // ---- extract first NBR ascending qualifiers of this segment ----
        // global index = seg + j*32 + lane  ->  ordered by (j, lane)
        int idx[NBR];
        #pragma unroll
        for (int k = 0; k < NBR; k++) idx[k] = 0;
        int cnt = 0;
        if (__ballot_sync(0xFFFFFFFFu, lm != 0)) {   // usually false for hard queries
            for (int j = 0; j < 32 && cnt < NBR; j++) {
                unsigned m = __ballot_sync(0xFFFFFFFFu, (lm >> j) & 1u);
                while (m && cnt < NBR) {
                    idx[cnt++] = seg + j * 32 + (__ffs(m) - 1);
                    m &= m - 1;
                }
            }
        }

        if (lane == 0) {
            s_cnt[wid] = cnt;
            #pragma unroll
            for (int k = 0; k < NBR; k++) s_list[wid][k] = idx[k];
        }
        __syncthreads();

        // ---- merge: segments ascending, lists internally ascending ----
        if (threadIdx.x == 0) {
            int tot = 0;
            #pragma unroll
            for (int ww = 0; ww < 8; ww++) {
                const int cw = s_cnt[ww];
                for (int k = 0; k < cw && tot < NBR; k++)
                    s_idx[tot++] = s_list[ww][k];
                if (tot >= NBR) break;
            }
            // tot >= 1 always (self point qualifies in its own segment)
            for (int k = tot; k < NBR; k++) s_idx[k] = s_idx[0];
        }
        __syncthreads();

        // ---- gather + max with 64 threads ----
        if (threadIdx.x < CC / 4) {
            const int t = threadIdx.x;
            const float* fb = feat + (size_t)b * NN * CC;
            const float4 a0 = ((const float4*)(fb + (size_t)s_idx[0] * CC))[t];
            const float4 a1 = ((const float4*)(fb + (size_t)s_idx[1] * CC))[t];
            const float4 a2 = ((const float4*)(fb + (size_t)s_idx[2] * CC))[t];
            const float4 a3 = ((const float4*)(fb + (size_t)s_idx[3] * CC))[t];
            float4 r;
            r.x = fmaxf(fmaxf(a0.x, a1.x), fmaxf(a2.x, a3.x));
            r.y = fmaxf(fmaxf(a0.y, a1.y), fmaxf(a2.y, a3.y));
            r.z = fmaxf(fmaxf(a0.z, a1.z), fmaxf(a2.z, a3.z));
            r.w = fmaxf(fmaxf(a0.w, a1.w), fmaxf(a2.w, a3.w));
            ((float4*)(outF + ((size_t)b * POOLN + s) * CC))[t] = r;
        }
        __syncthreads();   // protect s_* reuse across queries
    }
}

extern "C" void kernel_launch(void* const* d_in, const int* in_sizes, int n_in,
                              void* d_out, int out_size)
{
    const float* verts      = (const float*)d_in[0];
    const float* feat       = (const float*)d_in[1];
    const int*   radius_raw = (const int*)  d_in[2];
    const int*   sample_idx = (const int*)  d_in[3];

    float* outV = (float*)d_out;
    float* outF = (float*)d_out + (size_t)BB * POOLN * 3;

    pool_easy_kernel<<<BB * POOLN / QPB, 256>>>(verts, feat, radius_raw,
                                                sample_idx, outV, outF);
    pool_hard_kernel<<<BB * POOLN / QPB, 256>>>(verts, feat, radius_raw,
                                                sample_idx, outF);
}

// round 12
// speedup vs baseline: 1.5524x; 1.1943x over previous
#include <cuda_runtime.h>
#include <cuda_bf16.h>

#define BB     4
#define NN     8192
#define CC     256
#define POOLN  2048
#define NBR    4
#define TILE_PTS   2048                  // smem tile: first 2048 points of the batch
#define TILE_FLOATS (TILE_PTS * 3)       // 24 KB
#define QPB    8                         // queries (warps) per block
#define SEG    (NN / 8)                  // 1024 points per warp segment
#define HARD_GRID 512

__device__ int g_hard_list[BB * POOLN];
__device__ int g_hard_count;             // zero-init; consumed by hard, zeroed by reset node

__device__ __forceinline__ float decode_radius(const int* radius_raw)
{
    const unsigned rv = (unsigned)__ldg(radius_raw);
    return (rv & 0x7F800000u) ? __int_as_float((int)rv) : (float)(int)rv;
}

// ---------------- Easy pass: 8 queries per block, smem vertex tile ----------------
__global__ __launch_bounds__(256)
void pool_easy_kernel(const float* __restrict__ verts,
                      const float* __restrict__ feat,
                      const int*   __restrict__ radius_raw,
                      const int*   __restrict__ sample_idx,
                      float* __restrict__ outV,
                      float* __restrict__ outF)
{
    __shared__ float s_tile[TILE_FLOATS];   // raw (x,y,z)*2048 of this batch

    const int wid  = threadIdx.x >> 5;
    const int lane = threadIdx.x & 31;
    const int qid  = blockIdx.x * QPB + wid;         // 0 .. BB*POOLN-1
    const int b    = qid >> 11;                      // / POOLN (uniform per block)
    const int s    = qid & (POOLN - 1);

    // Cooperative tile load: 1536 float4 slots, coalesced.
    {
        const float4* __restrict__ src =
            (const float4*)(verts + (size_t)b * NN * 3);
        float4* dst = (float4*)s_tile;
        #pragma unroll
        for (int i = 0; i < TILE_FLOATS / 4 / 256; i++)
            dst[threadIdx.x + 256 * i] = src[threadIdx.x + 256 * i];
    }

    const int n = sample_idx[s];
    const float* vb = verts + (size_t)b * NN * 3;
    const float qx = vb[n * 3 + 0];
    const float qy = vb[n * 3 + 1];
    const float qz = vb[n * 3 + 2];
    const float sqn = qx * qx + qy * qy + qz * qz;

    const float radius = decode_radius(radius_raw);
    const float r2 = radius * radius;

    // vertices_pool (always written here)
    if (lane < 3) {
        const float v = (lane == 0) ? qx : (lane == 1) ? qy : qz;
        outV[((size_t)b * POOLN + s) * 3 + lane] = v;
    }

    __syncthreads();

    // ---- scan smem tile, first NBR ascending qualifiers ----
    int idx[NBR];
    int cnt = 0;
    #pragma unroll
    for (int k = 0; k < NBR; k++) idx[k] = n;

    for (int base = 0; base < TILE_PTS; base += 128) {
        unsigned bal[4];
        #pragma unroll
        for (int t = 0; t < 4; t++) {
            const int p = base + t * 32 + lane;
            const float px = s_tile[3 * p + 0];
            const float py = s_tile[3 * p + 1];
            const float pz = s_tile[3 * p + 2];
            const float d = -2.0f * (px * qx + py * qy + pz * qz) + sqn
                            + (px * px + py * py + pz * pz);
            bal[t] = __ballot_sync(0xFFFFFFFFu, !(d > r2));
        }
        #pragma unroll
        for (int t = 0; t < 4; t++) {
            unsigned m = bal[t];
            while (m && cnt < NBR) {
                idx[cnt++] = base + t * 32 + (__ffs(m) - 1);
                m &= m - 1;
            }
        }
        if (cnt >= NBR) break;   // uniform (ballot-derived)
    }

    if (cnt < NBR) {             // rare: defer to hard pass (compacted list)
        if (lane == 0) {
            const int pos = atomicAdd(&g_hard_count, 1);
            g_hard_list[pos] = qid;
        }
        return;
    }

    // ---- gather 4 feature rows (float4), max, store ----
    const float* fb = feat + (size_t)b * NN * CC;
    const float4* __restrict__ f0 = (const float4*)(fb + (size_t)idx[0] * CC);
    const float4* __restrict__ f1 = (const float4*)(fb + (size_t)idx[1] * CC);
    const float4* __restrict__ f2 = (const float4*)(fb + (size_t)idx[2] * CC);
    const float4* __restrict__ f3 = (const float4*)(fb + (size_t)idx[3] * CC);
    float4* __restrict__ fo = (float4*)(outF + ((size_t)b * POOLN + s) * CC);

    #pragma unroll
    for (int j = 0; j < CC / 128; j++) {
        const int c = lane + j * 32;
        float4 a = f0[c];
        const float4 v1 = f1[c], v2 = f2[c], v3 = f3[c];
        a.x = fmaxf(fmaxf(a.x, v1.x), fmaxf(v2.x, v3.x));
        a.y = fmaxf(fmaxf(a.y, v1.y), fmaxf(v2.y, v3.y));
        a.z = fmaxf(fmaxf(a.z, v1.z), fmaxf(v2.z, v3.z));
        a.w = fmaxf(fmaxf(a.w, v1.w), fmaxf(v2.w, v3.w));
        fo[c] = a;
    }
}

// ---------------- Hard pass: compacted list, <=1 query per block ----------------
// 8 coalesced warp segments, per-lane bitmask scan (staged loads, no ballots
// in the load loop), register-ballot extraction, segment-order merge.
// No done-counters, no self-reset (separate reset node follows).
__global__ __launch_bounds__(256, 2)
void pool_hard_kernel(const float* __restrict__ verts,
                      const float* __restrict__ feat,
                      const int*   __restrict__ radius_raw,
                      const int*   __restrict__ sample_idx,
                      float* __restrict__ outF)
{
    const int nhard = g_hard_count;
    if ((int)blockIdx.x >= nhard) return;

    const int wid  = threadIdx.x >> 5;
    const int lane = threadIdx.x & 31;

    __shared__ int s_cnt[8];
    __shared__ int s_list[8][NBR];
    __shared__ int s_idx[NBR];

    const float radius = decode_radius(radius_raw);
    const float r2 = radius * radius;

    for (int it = blockIdx.x; it < nhard; it += gridDim.x) {
        const int qid = g_hard_list[it];
        const int b = qid >> 11;
        const int s = qid & (POOLN - 1);

        const int n = sample_idx[s];
        const float* vb = verts + (size_t)b * NN * 3;
        const float qx = vb[n * 3 + 0];
        const float qy = vb[n * 3 + 1];
        const float qz = vb[n * 3 + 2];
        const float sqn = qx * qx + qy * qy + qz * qz;

        const int seg = wid * SEG;           // warp's 1024-point segment

        // ---- per-lane 32-bit qualifier mask; loads staged 16 points deep ----
        unsigned lm = 0;
        #pragma unroll
        for (int half = 0; half < 2; half++) {
            float vx[16], vy[16], vz[16];
            #pragma unroll
            for (int j = 0; j < 16; j++) {
                const int p = seg + (half * 16 + j) * 32 + lane;
                vx[j] = vb[3 * p + 0];
                vy[j] = vb[3 * p + 1];
                vz[j] = vb[3 * p + 2];
            }
            #pragma unroll
            for (int j = 0; j < 16; j++) {
                const float d = -2.0f * (vx[j] * qx + vy[j] * qy + vz[j] * qz) + sqn
                                + (vx[j] * vx[j] + vy[j] * vy[j] + vz[j] * vz[j]);
                lm |= ((unsigned)(!(d > r2))) << (half * 16 + j);
            }
        }

        // ---- extract first NBR ascending qualifiers of this segment ----
        // global index = seg + j*32 + lane  ->  ordered by (j, lane)
        int idx[NBR];
        #pragma unroll
        for (int k = 0; k < NBR; k++) idx[k] = 0;
        int cnt = 0;
        if (__ballot_sync(0xFFFFFFFFu, lm != 0)) {   // usually false for hard queries
            for (int j = 0; j < 32 && cnt < NBR; j++) {
                unsigned m = __ballot_sync(0xFFFFFFFFu, (lm >> j) & 1u);
                while (m && cnt < NBR) {
                    idx[cnt++] = seg + j * 32 + (__ffs(m) - 1);
                    m &= m - 1;
                }
            }
        }

        if (lane == 0) {
            s_cnt[wid] = cnt;
            #pragma unroll
            for (int k = 0; k < NBR; k++) s_list[wid][k] = idx[k];
        }
        __syncthreads();

        // ---- merge: segments ascending, lists internally ascending ----
        if (threadIdx.x == 0) {
            int tot = 0;
            #pragma unroll
            for (int ww = 0; ww < 8; ww++) {
                const int cw = s_cnt[ww];
                for (int k = 0; k < cw && tot < NBR; k++)
                    s_idx[tot++] = s_list[ww][k];
                if (tot >= NBR) break;
            }
            // tot >= 1 always (self point qualifies in its own segment)
            for (int k = tot; k < NBR; k++) s_idx[k] = s_idx[0];
        }
        __syncthreads();

        // ---- gather + max with 64 threads ----
        if (threadIdx.x < CC / 4) {
            const int t = threadIdx.x;
            const float* fb = feat + (size_t)b * NN * CC;
            const float4 a0 = ((const float4*)(fb + (size_t)s_idx[0] * CC))[t];
            const float4 a1 = ((const float4*)(fb + (size_t)s_idx[1] * CC))[t];
            const float4 a2 = ((const float4*)(fb + (size_t)s_idx[2] * CC))[t];
            const float4 a3 = ((const float4*)(fb + (size_t)s_idx[3] * CC))[t];
            float4 r;
            r.x = fmaxf(fmaxf(a0.x, a1.x), fmaxf(a2.x, a3.x));
            r.y = fmaxf(fmaxf(a0.y, a1.y), fmaxf(a2.y, a3.y));
            r.z = fmaxf(fmaxf(a0.z, a1.z), fmaxf(a2.z, a3.z));
            r.w = fmaxf(fmaxf(a0.w, a1.w), fmaxf(a2.w, a3.w));
            ((float4*)(outF + ((size_t)b * POOLN + s) * CC))[t] = r;
        }
        __syncthreads();   // protect s_* reuse (only if nhard > gridDim.x)
    }
}

// ---------------- Reset node: restore counter for next replay ----------------
__global__ void reset_kernel()
{
    g_hard_count = 0;
}

extern "C" void kernel_launch(void* const* d_in, const int* in_sizes, int n_in,
                              void* d_out, int out_size)
{
    const float* verts      = (const float*)d_in[0];
    const float* feat       = (const float*)d_in[1];
    const int*   radius_raw = (const int*)  d_in[2];
    const int*   sample_idx = (const int*)  d_in[3];

    float* outV = (float*)d_out;
    float* outF = (float*)d_out + (size_t)BB * POOLN * 3;

    pool_easy_kernel<<<BB * POOLN / QPB, 256>>>(verts, feat, radius_raw,
                                                sample_idx, outV, outF);
    pool_hard_kernel<<<HARD_GRID, 256>>>(verts, feat, radius_raw, sample_idx, outF);
    reset_kernel<<<1, 1>>>();
}

// round 13
// speedup vs baseline: 1.5927x; 1.0260x over previous
#include <cuda_runtime.h>
#include <cuda_bf16.h>

#define BB     4
#define NN     8192
#define CC     256
#define POOLN  2048
#define NBR    4
#define TILE_PTS   1024                  // smem tile: first 1024 points of the batch
#define TILE_FLOATS (TILE_PTS * 3)       // 12 KB
#define QPB    16                        // queries (warps) per block
#define NTHREADS 512
#define SEG    (NN / 8)                  // 1024 points per warp segment (hard pass)
#define HARD_GRID 512

__device__ int g_hard_list[BB * POOLN];
__device__ int g_hard_count;             // zero-init; consumed by hard, zeroed by reset node

__device__ __forceinline__ float decode_radius(const int* radius_raw)
{
    const unsigned rv = (unsigned)__ldg(radius_raw);
    return (rv & 0x7F800000u) ? __int_as_float((int)rv) : (float)(int)rv;
}

// ---------------- Easy pass: 16 queries per 512-thread block ----------------
__global__ __launch_bounds__(NTHREADS)
void pool_easy_kernel(const float* __restrict__ verts,
                      const float* __restrict__ feat,
                      const int*   __restrict__ radius_raw,
                      const int*   __restrict__ sample_idx,
                      float* __restrict__ outV,
                      float* __restrict__ outF)
{
    __shared__ float s_tile[TILE_FLOATS];   // raw (x,y,z)*1024 of this batch

    const int wid  = threadIdx.x >> 5;
    const int lane = threadIdx.x & 31;
    const int qid  = blockIdx.x * QPB + wid;         // 0 .. BB*POOLN-1
    const int b    = qid >> 11;                      // / POOLN (uniform per block)
    const int s    = qid & (POOLN - 1);

    // Cooperative tile load: 768 float4 slots, coalesced.
    {
        const float4* __restrict__ src =
            (const float4*)(verts + (size_t)b * NN * 3);
        float4* dst = (float4*)s_tile;
        for (int i = threadIdx.x; i < TILE_FLOATS / 4; i += NTHREADS)
            dst[i] = src[i];
    }

    const int n = sample_idx[s];
    const float* vb = verts + (size_t)b * NN * 3;
    const float qx = vb[n * 3 + 0];
    const float qy = vb[n * 3 + 1];
    const float qz = vb[n * 3 + 2];
    const float sqn = qx * qx + qy * qy + qz * qz;

    const float radius = decode_radius(radius_raw);
    const float r2 = radius * radius;

    // vertices_pool (always written here)
    if (lane < 3) {
        const float v = (lane == 0) ? qx : (lane == 1) ? qy : qz;
        outV[((size_t)b * POOLN + s) * 3 + lane] = v;
    }

    __syncthreads();

    // ---- scan smem tile, first NBR ascending qualifiers ----
    int idx[NBR];
    int cnt = 0;
    #pragma unroll
    for (int k = 0; k < NBR; k++) idx[k] = n;

    for (int base = 0; base < TILE_PTS; base += 128) {
        unsigned bal[4];
        #pragma unroll
        for (int t = 0; t < 4; t++) {
            const int p = base + t * 32 + lane;
            const float px = s_tile[3 * p + 0];
            const float py = s_tile[3 * p + 1];
            const float pz = s_tile[3 * p + 2];
            const float d = -2.0f * (px * qx + py * qy + pz * qz) + sqn
                            + (px * px + py * py + pz * pz);
            bal[t] = __ballot_sync(0xFFFFFFFFu, !(d > r2));
        }
        #pragma unroll
        for (int t = 0; t < 4; t++) {
            unsigned m = bal[t];
            while (m && cnt < NBR) {
                idx[cnt++] = base + t * 32 + (__ffs(m) - 1);
                m &= m - 1;
            }
        }
        if (cnt >= NBR) break;   // uniform (ballot-derived)
    }

    if (cnt < NBR) {             // defer to hard pass (compacted list)
        if (lane == 0) {
            const int pos = atomicAdd(&g_hard_count, 1);
            g_hard_list[pos] = qid;
        }
        return;
    }

    // ---- gather 4 feature rows: all 8 float4 loads in flight, then max ----
    const float* fb = feat + (size_t)b * NN * CC;
    const float4* __restrict__ f0 = (const float4*)(fb + (size_t)idx[0] * CC);
    const float4* __restrict__ f1 = (const float4*)(fb + (size_t)idx[1] * CC);
    const float4* __restrict__ f2 = (const float4*)(fb + (size_t)idx[2] * CC);
    const float4* __restrict__ f3 = (const float4*)(fb + (size_t)idx[3] * CC);
    float4* __restrict__ fo = (float4*)(outF + ((size_t)b * POOLN + s) * CC);

    const int c0 = lane;
    const int c1 = lane + 32;
    float4 a0 = f0[c0], b0 = f1[c0], e0 = f2[c0], g0 = f3[c0];
    float4 a1 = f0[c1], b1 = f1[c1], e1 = f2[c1], g1 = f3[c1];

    float4 r0, r1;
    r0.x = fmaxf(fmaxf(a0.x, b0.x), fmaxf(e0.x, g0.x));
    r0.y = fmaxf(fmaxf(a0.y, b0.y), fmaxf(e0.y, g0.y));
    r0.z = fmaxf(fmaxf(a0.z, b0.z), fmaxf(e0.z, g0.z));
    r0.w = fmaxf(fmaxf(a0.w, b0.w), fmaxf(e0.w, g0.w));
    r1.x = fmaxf(fmaxf(a1.x, b1.x), fmaxf(e1.x, g1.x));
    r1.y = fmaxf(fmaxf(a1.y, b1.y), fmaxf(e1.y, g1.y));
    r1.z = fmaxf(fmaxf(a1.z, b1.z), fmaxf(e1.z, g1.z));
    r1.w = fmaxf(fmaxf(a1.w, b1.w), fmaxf(e1.w, g1.w));
    fo[c0] = r0;
    fo[c1] = r1;
}

// ---------------- Hard pass: compacted list, <=1 query per block ----------------
__global__ __launch_bounds__(256, 2)
void pool_hard_kernel(const float* __restrict__ verts,
                      const float* __restrict__ feat,
                      const int*   __restrict__ radius_raw,
                      const int*   __restrict__ sample_idx,
                      float* __restrict__ outF)
{
    const int nhard = g_hard_count;
    if ((int)blockIdx.x >= nhard) return;

    const int wid  = threadIdx.x >> 5;
    const int lane = threadIdx.x & 31;

    __shared__ int s_cnt[8];
    __shared__ int s_list[8][NBR];
    __shared__ int s_idx[NBR];

    const float radius = decode_radius(radius_raw);
    const float r2 = radius * radius;

    for (int it = blockIdx.x; it < nhard; it += gridDim.x) {
        const int qid = g_hard_list[it];
        const int b = qid >> 11;
        const int s = qid & (POOLN - 1);

        const int n = sample_idx[s];
        const float* vb = verts + (size_t)b * NN * 3;
        const float qx = vb[n * 3 + 0];
        const float qy = vb[n * 3 + 1];
        const float qz = vb[n * 3 + 2];
        const float sqn = qx * qx + qy * qy + qz * qz;

        const int seg = wid * SEG;           // warp's 1024-point segment

        // ---- per-lane 32-bit qualifier mask; loads staged 16 points deep ----
        unsigned lm = 0;
        #pragma unroll
        for (int half = 0; half < 2; half++) {
            float vx[16], vy[16], vz[16];
            #pragma unroll
            for (int j = 0; j < 16; j++) {
                const int p = seg + (half * 16 + j) * 32 + lane;
                vx[j] = vb[3 * p + 0];
                vy[j] = vb[3 * p + 1];
                vz[j] = vb[3 * p + 2];
            }
            #pragma unroll
            for (int j = 0; j < 16; j++) {
                const float d = -2.0f * (vx[j] * qx + vy[j] * qy + vz[j] * qz) + sqn
                                + (vx[j] * vx[j] + vy[j] * vy[j] + vz[j] * vz[j]);
                lm |= ((unsigned)(!(d > r2))) << (half * 16 + j);
            }
        }

        // ---- extract first NBR ascending qualifiers of this segment ----
        int idx[NBR];
        #pragma unroll
        for (int k = 0; k < NBR; k++) idx[k] = 0;
        int cnt = 0;
        if (__ballot_sync(0xFFFFFFFFu, lm != 0)) {   // usually false for hard queries
            for (int j = 0; j < 32 && cnt < NBR; j++) {
                unsigned m = __ballot_sync(0xFFFFFFFFu, (lm >> j) & 1u);
                while (m && cnt < NBR) {
                    idx[cnt++] = seg + j * 32 + (__ffs(m) - 1);
                    m &= m - 1;
                }
            }
        }

        if (lane == 0) {
            s_cnt[wid] = cnt;
            #pragma unroll
            for (int k = 0; k < NBR; k++) s_list[wid][k] = idx[k];
        }
        __syncthreads();

        // ---- merge: segments ascending, lists internally ascending ----
        if (threadIdx.x == 0) {
            int tot = 0;
            #pragma unroll
            for (int ww = 0; ww < 8; ww++) {
                const int cw = s_cnt[ww];
                for (int k = 0; k < cw && tot < NBR; k++)
                    s_idx[tot++] = s_list[ww][k];
                if (tot >= NBR) break;
            }
            for (int k = tot; k < NBR; k++) s_idx[k] = s_idx[0];
        }
        __syncthreads();

        // ---- gather + max with 64 threads ----
        if (threadIdx.x < CC / 4) {
            const int t = threadIdx.x;
            const float* fb = feat + (size_t)b * NN * CC;
            const float4 a0 = ((const float4*)(fb + (size_t)s_idx[0] * CC))[t];
            const float4 a1 = ((const float4*)(fb + (size_t)s_idx[1] * CC))[t];
            const float4 a2 = ((const float4*)(fb + (size_t)s_idx[2] * CC))[t];
            const float4 a3 = ((const float4*)(fb + (size_t)s_idx[3] * CC))[t];
            float4 r;
            r.x = fmaxf(fmaxf(a0.x, a1.x), fmaxf(a2.x, a3.x));
            r.y = fmaxf(fmaxf(a0.y, a1.y), fmaxf(a2.y, a3.y));
            r.z = fmaxf(fmaxf(a0.z, a1.z), fmaxf(a2.z, a3.z));
            r.w = fmaxf(fmaxf(a0.w, a1.w), fmaxf(a2.w, a3.w));
            ((float4*)(outF + ((size_t)b * POOLN + s) * CC))[t] = r;
        }
        __syncthreads();   // protect s_* reuse (only if nhard > gridDim.x)
    }
}

// ---------------- Reset node: restore counter for next replay ----------------
__global__ void reset_kernel()
{
    g_hard_count = 0;
}

extern "C" void kernel_launch(void* const* d_in, const int* in_sizes, int n_in,
                              void* d_out, int out_size)
{
    const float* verts      = (const float*)d_in[0];
    const float* feat       = (const float*)d_in[1];
    const int*   radius_raw = (const int*)  d_in[2];
    const int*   sample_idx = (const int*)  d_in[3];

    float* outV = (float*)d_out;
    float* outF = (float*)d_out + (size_t)BB * POOLN * 3;

    pool_easy_kernel<<<BB * POOLN / QPB, NTHREADS>>>(verts, feat, radius_raw,
                                                     sample_idx, outV, outF);
    pool_hard_kernel<<<HARD_GRID, 256>>>(verts, feat, radius_raw, sample_idx, outF);
    reset_kernel<<<1, 1>>>();
}

// round 14
// speedup vs baseline: 1.7405x; 1.0928x over previous
#include <cuda_runtime.h>
#include <cuda_bf16.h>

#define BB     4
#define NN     8192
#define CC     256
#define POOLN  2048
#define NBR    4
#define TILE_PTS   1024                  // smem tile: first 1024 points of the batch
#define QPB    16                        // queries (warps) per block
#define NTHREADS 512
#define SEG    (NN / 8)                  // 1024 points per warp segment (hard pass)
#define HARD_GRID 512

__device__ int g_hard_list[BB * POOLN];
__device__ int g_hard_count;             // zero-init; consumed by hard, zeroed by reset node

__device__ __forceinline__ float decode_radius(const int* radius_raw)
{
    const unsigned rv = (unsigned)__ldg(radius_raw);
    return (rv & 0x7F800000u) ? __int_as_float((int)rv) : (float)(int)rv;
}

// ---------------- Easy pass: 16 queries per 512-thread block ----------------
// smem tile packed as float4 (x, y, z, |p|^2): one LDS.128 per scanned point,
// norms computed once per point at load time instead of per warp per point.
__global__ __launch_bounds__(NTHREADS)
void pool_easy_kernel(const float* __restrict__ verts,
                      const float* __restrict__ feat,
                      const int*   __restrict__ radius_raw,
                      const int*   __restrict__ sample_idx,
                      float* __restrict__ outV,
                      float* __restrict__ outF)
{
    __shared__ float4 s_tile[TILE_PTS];   // 16 KB

    const int wid  = threadIdx.x >> 5;
    const int lane = threadIdx.x & 31;
    const int qid  = blockIdx.x * QPB + wid;         // 0 .. BB*POOLN-1
    const int b    = qid >> 11;                      // / POOLN (uniform per block)
    const int s    = qid & (POOLN - 1);

    const float* vb = verts + (size_t)b * NN * 3;

    // Cooperative packed tile load: 2 points per thread.
    {
        #pragma unroll
        for (int i = 0; i < TILE_PTS / NTHREADS; i++) {
            const int p = threadIdx.x + i * NTHREADS;
            const float px = vb[3 * p + 0];
            const float py = vb[3 * p + 1];
            const float pz = vb[3 * p + 2];
            s_tile[p] = make_float4(px, py, pz, px * px + py * py + pz * pz);
        }
    }

    const int n = sample_idx[s];
    const float qx = vb[n * 3 + 0];
    const float qy = vb[n * 3 + 1];
    const float qz = vb[n * 3 + 2];
    const float sqn = qx * qx + qy * qy + qz * qz;

    const float radius = decode_radius(radius_raw);
    const float r2 = radius * radius;

    // vertices_pool (always written here)
    if (lane < 3) {
        const float v = (lane == 0) ? qx : (lane == 1) ? qy : qz;
        outV[((size_t)b * POOLN + s) * 3 + lane] = v;
    }

    __syncthreads();

    // ---- scan packed smem tile, first NBR ascending qualifiers ----
    int idx[NBR];
    int cnt = 0;
    #pragma unroll
    for (int k = 0; k < NBR; k++) idx[k] = n;

    for (int base = 0; base < TILE_PTS; base += 128) {
        unsigned bal[4];
        #pragma unroll
        for (int t = 0; t < 4; t++) {
            const float4 P = s_tile[base + t * 32 + lane];
            // same evaluation order as reference: (-2*dot + sq_n) + sq_m
            const float d = -2.0f * (P.x * qx + P.y * qy + P.z * qz) + sqn + P.w;
            bal[t] = __ballot_sync(0xFFFFFFFFu, !(d > r2));
        }
        #pragma unroll
        for (int t = 0; t < 4; t++) {
            unsigned m = bal[t];
            while (m && cnt < NBR) {
                idx[cnt++] = base + t * 32 + (__ffs(m) - 1);
                m &= m - 1;
            }
        }
        if (cnt >= NBR) break;   // uniform (ballot-derived)
    }

    if (cnt < NBR) {             // defer to hard pass (compacted list)
        if (lane == 0) {
            const int pos = atomicAdd(&g_hard_count, 1);
            g_hard_list[pos] = qid;
        }
        return;
    }

    // ---- gather 4 feature rows: all 8 float4 loads in flight, then max ----
    const float* fb = feat + (size_t)b * NN * CC;
    const float4* __restrict__ f0 = (const float4*)(fb + (size_t)idx[0] * CC);
    const float4* __restrict__ f1 = (const float4*)(fb + (size_t)idx[1] * CC);
    const float4* __restrict__ f2 = (const float4*)(fb + (size_t)idx[2] * CC);
    const float4* __restrict__ f3 = (const float4*)(fb + (size_t)idx[3] * CC);
    float4* __restrict__ fo = (float4*)(outF + ((size_t)b * POOLN + s) * CC);

    const int c0 = lane;
    const int c1 = lane + 32;
    float4 a0 = f0[c0], b0 = f1[c0], e0 = f2[c0], g0 = f3[c0];
    float4 a1 = f0[c1], b1 = f1[c1], e1 = f2[c1], g1 = f3[c1];

    float4 r0, r1;
    r0.x = fmaxf(fmaxf(a0.x, b0.x), fmaxf(e0.x, g0.x));
    r0.y = fmaxf(fmaxf(a0.y, b0.y), fmaxf(e0.y, g0.y));
    r0.z = fmaxf(fmaxf(a0.z, b0.z), fmaxf(e0.z, g0.z));
    r0.w = fmaxf(fmaxf(a0.w, b0.w), fmaxf(e0.w, g0.w));
    r1.x = fmaxf(fmaxf(a1.x, b1.x), fmaxf(e1.x, g1.x));
    r1.y = fmaxf(fmaxf(a1.y, b1.y), fmaxf(e1.y, g1.y));
    r1.z = fmaxf(fmaxf(a1.z, b1.z), fmaxf(e1.z, g1.z));
    r1.w = fmaxf(fmaxf(a1.w, b1.w), fmaxf(e1.w, g1.w));
    fo[c0] = r0;
    fo[c1] = r1;
}

// ---------------- Hard pass: compacted list, <=1 query per block ----------------
__global__ __launch_bounds__(256, 2)
void pool_hard_kernel(const float* __restrict__ verts,
                      const float* __restrict__ feat,
                      const int*   __restrict__ radius_raw,
                      const int*   __restrict__ sample_idx,
                      float* __restrict__ outF)
{
    const int nhard = g_hard_count;
    if ((int)blockIdx.x >= nhard) return;

    const int wid  = threadIdx.x >> 5;
    const int lane = threadIdx.x & 31;

    __shared__ int s_cnt[8];
    __shared__ int s_list[8][NBR];
    __shared__ int s_idx[NBR];

    const float radius = decode_radius(radius_raw);
    const float r2 = radius * radius;

    for (int it = blockIdx.x; it < nhard; it += gridDim.x) {
        const int qid = g_hard_list[it];
        const int b = qid >> 11;
        const int s = qid & (POOLN - 1);

        const int n = sample_idx[s];
        const float* vb = verts + (size_t)b * NN * 3;
        const float qx = vb[n * 3 + 0];
        const float qy = vb[n * 3 + 1];
        const float qz = vb[n * 3 + 2];
        const float sqn = qx * qx + qy * qy + qz * qz;

        const int seg = wid * SEG;           // warp's 1024-point segment

        // ---- per-lane 32-bit qualifier mask; loads staged 16 points deep ----
        unsigned lm = 0;
        #pragma unroll
        for (int half = 0; half < 2; half++) {
            float vx[16], vy[16], vz[16];
            #pragma unroll
            for (int j = 0; j < 16; j++) {
                const int p = seg + (half * 16 + j) * 32 + lane;
                vx[j] = vb[3 * p + 0];
                vy[j] = vb[3 * p + 1];
                vz[j] = vb[3 * p + 2];
            }
            #pragma unroll
            for (int j = 0; j < 16; j++) {
                const float d = -2.0f * (vx[j] * qx + vy[j] * qy + vz[j] * qz) + sqn
                                + (vx[j] * vx[j] + vy[j] * vy[j] + vz[j] * vz[j]);
                lm |= ((unsigned)(!(d > r2))) << (half * 16 + j);
            }
        }

        // ---- extract first NBR ascending qualifiers of this segment ----
        int idx[NBR];
        #pragma unroll
        for (int k = 0; k < NBR; k++) idx[k] = 0;
        int cnt = 0;
        if (__ballot_sync(0xFFFFFFFFu, lm != 0)) {   // usually false for hard queries
            for (int j = 0; j < 32 && cnt < NBR; j++) {
                unsigned m = __ballot_sync(0xFFFFFFFFu, (lm >> j) & 1u);
                while (m && cnt < NBR) {
                    idx[cnt++] = seg + j * 32 + (__ffs(m) - 1);
                    m &= m - 1;
                }
            }
        }

        if (lane == 0) {
            s_cnt[wid] = cnt;
            #pragma unroll
            for (int k = 0; k < NBR; k++) s_list[wid][k] = idx[k];
        }
        __syncthreads();

        // ---- merge: segments ascending, lists internally ascending ----
        if (threadIdx.x == 0) {
            int tot = 0;
            #pragma unroll
            for (int ww = 0; ww < 8; ww++) {
                const int cw = s_cnt[ww];
                for (int k = 0; k < cw && tot < NBR; k++)
                    s_idx[tot++] = s_list[ww][k];
                if (tot >= NBR) break;
            }
            for (int k = tot; k < NBR; k++) s_idx[k] = s_idx[0];
        }
        __syncthreads();

        // ---- gather + max with 64 threads ----
        if (threadIdx.x < CC / 4) {
            const int t = threadIdx.x;
            const float* fb = feat + (size_t)b * NN * CC;
            const float4 a0 = ((const float4*)(fb + (size_t)s_idx[0] * CC))[t];
            const float4 a1 = ((const float4*)(fb + (size_t)s_idx[1] * CC))[t];
            const float4 a2 = ((const float4*)(fb + (size_t)s_idx[2] * CC))[t];
            const float4 a3 = ((const float4*)(fb + (size_t)s_idx[3] * CC))[t];
            float4 r;
            r.x = fmaxf(fmaxf(a0.x, a1.x), fmaxf(a2.x, a3.x));
            r.y = fmaxf(fmaxf(a0.y, a1.y), fmaxf(a2.y, a3.y));
            r.z = fmaxf(fmaxf(a0.z, a1.z), fmaxf(a2.z, a3.z));
            r.w = fmaxf(fmaxf(a0.w, a1.w), fmaxf(a2.w, a3.w));
            ((float4*)(outF + ((size_t)b * POOLN + s) * CC))[t] = r;
        }
        __syncthreads();   // protect s_* reuse (only if nhard > gridDim.x)
    }
}

// ---------------- Reset node: restore counter for next replay ----------------
__global__ void reset_kernel()
{
    g_hard_count = 0;
}

extern "C" void kernel_launch(void* const* d_in, const int* in_sizes, int n_in,
                              void* d_out, int out_size)
{
    const float* verts      = (const float*)d_in[0];
    const float* feat       = (const float*)d_in[1];
    const int*   radius_raw = (const int*)  d_in[2];
    const int*   sample_idx = (const int*)  d_in[3];

    float* outV = (float*)d_out;
    float* outF = (float*)d_out + (size_t)BB * POOLN * 3;

    pool_easy_kernel<<<BB * POOLN / QPB, NTHREADS>>>(verts, feat, radius_raw,
                                                     sample_idx, outV, outF);
    pool_hard_kernel<<<HARD_GRID, 256>>>(verts, feat, radius_raw, sample_idx, outF);
    reset_kernel<<<1, 1>>>();
}